// round 2
// baseline (speedup 1.0000x reference)
#include <cuda_runtime.h>

#define N_NODES 50000
#define N_EDGES 800000
#define HIDDEN  128
#define H4      512   // 4*HIDDEN

// Precomputed P = emb @ W1[:128] + b1, Q = emb @ W1[128:]   ([N_NODES, 512] each)
__device__ float g_P[(size_t)N_NODES * H4];
__device__ float g_Q[(size_t)N_NODES * H4];
__device__ int   g_idx64;   // 1 if edge_index is int64, 0 if int32

typedef unsigned long long ull;

__device__ __forceinline__ ull pk2(float x, float y) {
    ull r; asm("mov.b64 %0, {%1, %2};" : "=l"(r) : "f"(x), "f"(y)); return r;
}
__device__ __forceinline__ void upk2(ull v, float& x, float& y) {
    asm("mov.b64 {%0, %1}, %2;" : "=f"(x), "=f"(y) : "l"(v));
}
__device__ __forceinline__ void fma2(ull& d, ull a, ull b) {
    asm("fma.rn.f32x2 %0, %1, %2, %0;" : "+l"(d) : "l"(a), "l"(b));
}

// ---------------------------------------------------------------------------
// Kernel 0: dtype detection for edge_index.
// If int64 (values in [0, 50000)), every odd int32 word of the first 128
// elements is zero. Under int32, those words are random node ids.
// ---------------------------------------------------------------------------
__global__ void detect_kernel(const int* __restrict__ ei32)
{
    int t = threadIdx.x;                 // 128 threads
    int w = ei32[2 * t + 1];             // odd word
    unsigned ballot = __ballot_sync(0xFFFFFFFFu, w != 0);
    __shared__ int any_nz;
    if (t == 0) any_nz = 0;
    __syncthreads();
    if ((t & 31) == 0 && ballot) atomicOr(&any_nz, 1);
    __syncthreads();
    if (t == 0) g_idx64 = any_nz ? 0 : 1;
}

// ---------------------------------------------------------------------------
// Kernel 1: P/Q precompute.  C[64 nodes, 128 outs] tiles, K=128 in chunks of 32.
// grid: (ceil(N/64), 512/128, 2)   z=0 -> P (+b1), z=1 -> Q
// ---------------------------------------------------------------------------
__global__ __launch_bounds__(256) void pq_kernel(
    const float* __restrict__ emb,
    const float* __restrict__ W1,
    const float* __restrict__ b1)
{
    __shared__ float A_s[64 * 36];   // [node][k], pad 36
    __shared__ float B_s[32 * 128];  // [k][j]

    const int t   = threadIdx.x;
    const int n0  = blockIdx.x * 64;
    const int j0t = blockIdx.y * 128;
    const int z   = blockIdx.z;
    float* gout = z ? g_Q : g_P;
    const float* Wbase = W1 + (size_t)z * HIDDEN * H4;

    ull acc[4][4];
#pragma unroll
    for (int i = 0; i < 4; i++)
#pragma unroll
        for (int p = 0; p < 4; p++) acc[i][p] = 0ull;

    const int e0 = (t >> 4) * 4;     // node sub-offset (0..60)
    const int j0 = (t & 15) * 8;     // out sub-offset  (0..120)

    for (int kc = 0; kc < HIDDEN; kc += 32) {
        // stage A: 64 nodes x 32 k  (float4 per 8-thread group)
#pragma unroll
        for (int i = 0; i < 2; i++) {
            int u  = t + i * 256;
            int nl = u >> 3;
            int k4 = (u & 7) * 4;
            int n  = n0 + nl; if (n >= N_NODES) n = N_NODES - 1;
            float4 v = *(const float4*)(emb + (size_t)n * HIDDEN + kc + k4);
            *(float4*)&A_s[nl * 36 + k4] = v;
        }
        // stage B: 32 k x 128 j
#pragma unroll
        for (int i = 0; i < 4; i++) {
            int f  = t + i * 256;        // float4 index over 1024
            int k  = f >> 5;
            int j4 = (f & 31) * 4;
            float4 v = *(const float4*)(Wbase + (size_t)(kc + k) * H4 + j0t + j4);
            *(float4*)&B_s[k * 128 + j4] = v;
        }
        __syncthreads();
#pragma unroll 8
        for (int kk = 0; kk < 32; kk++) {
            float4 bA = *(float4*)&B_s[kk * 128 + j0];
            float4 bB = *(float4*)&B_s[kk * 128 + j0 + 4];
            ull pb0 = pk2(bA.x, bA.y), pb1 = pk2(bA.z, bA.w);
            ull pb2 = pk2(bB.x, bB.y), pb3 = pk2(bB.z, bB.w);
#pragma unroll
            for (int i = 0; i < 4; i++) {
                float a = A_s[(e0 + i) * 36 + kk];
                ull pa = pk2(a, a);
                fma2(acc[i][0], pa, pb0);
                fma2(acc[i][1], pa, pb1);
                fma2(acc[i][2], pa, pb2);
                fma2(acc[i][3], pa, pb3);
            }
        }
        __syncthreads();
    }

#pragma unroll
    for (int i = 0; i < 4; i++) {
        int n = n0 + e0 + i;
        if (n < N_NODES) {
#pragma unroll
            for (int p = 0; p < 4; p++) {
                float x, y; upk2(acc[i][p], x, y);
                int j = j0t + j0 + p * 2;
                if (z == 0) { x += b1[j]; y += b1[j + 1]; }
                float2 v = make_float2(x, y);
                *(float2*)(&gout[(size_t)n * H4 + j]) = v;
            }
        }
    }
}

// ---------------------------------------------------------------------------
// Kernel 2: per-edge  x1 = relu(P[col]+Q[row]);  x2 = relu(x1@W2+b2);
//           out = x2 @ W3 + b3.   Tile: 64 edges x 128 outs, K=512 in 16 chunks.
// ---------------------------------------------------------------------------
__global__ __launch_bounds__(256) void edge_kernel(
    const void* __restrict__ ei,
    const float* __restrict__ W2,
    const float* __restrict__ b2,
    const float* __restrict__ W3,
    const float* __restrict__ b3,
    float* __restrict__ out)
{
    __shared__ float A_s[64 * 36];   // [edge][k], pad 36
    __shared__ float B_s[32 * 128];  // [k][j]
    __shared__ int   s_col[64], s_row[64];
    __shared__ float s_b2[128], s_w3[128];
    __shared__ float red[64][17];

    const int t  = threadIdx.x;
    const long long eb = (long long)blockIdx.x * 64;

    if (t < 64) {
        long long e = eb + t;
        int c, r;
        if (g_idx64) {
            const long long* p = (const long long*)ei;
            c = (int)p[e];
            r = (int)p[(long long)N_EDGES + e];
        } else {
            const int* p = (const int*)ei;
            c = p[e];
            r = p[(long long)N_EDGES + e];
        }
        // defensive clamp: a bad index becomes a wrong value (caught by
        // rel_err), not an uninformative IMA
        c = min(max(c, 0), N_NODES - 1);
        r = min(max(r, 0), N_NODES - 1);
        s_col[t] = c;
        s_row[t] = r;
    } else if (t < 192) {
        int j = t - 64;
        s_b2[j] = b2[j];
        s_w3[j] = W3[j];
    }
    __syncthreads();

    ull acc[4][4];
#pragma unroll
    for (int i = 0; i < 4; i++)
#pragma unroll
        for (int p = 0; p < 4; p++) acc[i][p] = 0ull;

    const int e0 = (t >> 4) * 4;
    const int j0 = (t & 15) * 8;

    for (int kc = 0; kc < H4; kc += 32) {
        // stage A: x1[e][k] = relu(P[col_e][k] + Q[row_e][k])
#pragma unroll
        for (int i = 0; i < 2; i++) {
            int u  = t + i * 256;
            int el = u >> 3;
            int k4 = (u & 7) * 4;
            const float4 p = *(const float4*)(g_P + (size_t)s_col[el] * H4 + kc + k4);
            const float4 q = *(const float4*)(g_Q + (size_t)s_row[el] * H4 + kc + k4);
            float4 v;
            v.x = fmaxf(p.x + q.x, 0.f);
            v.y = fmaxf(p.y + q.y, 0.f);
            v.z = fmaxf(p.z + q.z, 0.f);
            v.w = fmaxf(p.w + q.w, 0.f);
            *(float4*)&A_s[el * 36 + k4] = v;
        }
        // stage B: W2 rows kc..kc+31  (row length 128)
#pragma unroll
        for (int i = 0; i < 4; i++) {
            int f  = t + i * 256;
            int k  = f >> 5;
            int j4 = (f & 31) * 4;
            float4 v = *(const float4*)(W2 + (size_t)(kc + k) * HIDDEN + j4);
            *(float4*)&B_s[k * 128 + j4] = v;
        }
        __syncthreads();
#pragma unroll 8
        for (int kk = 0; kk < 32; kk++) {
            float4 bA = *(float4*)&B_s[kk * 128 + j0];
            float4 bB = *(float4*)&B_s[kk * 128 + j0 + 4];
            ull pb0 = pk2(bA.x, bA.y), pb1 = pk2(bA.z, bA.w);
            ull pb2 = pk2(bB.x, bB.y), pb3 = pk2(bB.z, bB.w);
#pragma unroll
            for (int i = 0; i < 4; i++) {
                float a = A_s[(e0 + i) * 36 + kk];
                ull pa = pk2(a, a);
                fma2(acc[i][0], pa, pb0);
                fma2(acc[i][1], pa, pb1);
                fma2(acc[i][2], pa, pb2);
                fma2(acc[i][3], pa, pb3);
            }
        }
        __syncthreads();
    }

    // layer-3 fold: out_e = sum_j relu(x2_pre[j] + b2[j]) * W3[j]  (+ b3)
    float part[4];
#pragma unroll
    for (int i = 0; i < 4; i++) {
        float s = 0.f;
#pragma unroll
        for (int p = 0; p < 4; p++) {
            float x, y; upk2(acc[i][p], x, y);
            int j = j0 + p * 2;
            s += fmaxf(x + s_b2[j],     0.f) * s_w3[j];
            s += fmaxf(y + s_b2[j + 1], 0.f) * s_w3[j + 1];
        }
        part[i] = s;
    }
    const int tj = t & 15;
#pragma unroll
    for (int i = 0; i < 4; i++) red[e0 + i][tj] = part[i];
    __syncthreads();
    if (t < 64) {
        float s = b3[0];
#pragma unroll
        for (int u = 0; u < 16; u++) s += red[t][u];
        out[eb + t] = s;
    }
}

extern "C" void kernel_launch(void* const* d_in, const int* in_sizes, int n_in,
                              void* d_out, int out_size)
{
    const float* emb = (const float*)d_in[0];
    const void*  ei  = d_in[1];
    const float* W1  = (const float*)d_in[2];
    const float* b1  = (const float*)d_in[3];
    const float* W2  = (const float*)d_in[4];
    const float* b2  = (const float*)d_in[5];
    const float* W3  = (const float*)d_in[6];
    const float* b3  = (const float*)d_in[7];
    float* out = (float*)d_out;
    (void)in_sizes; (void)n_in; (void)out_size;

    detect_kernel<<<1, 128>>>((const int*)ei);
    dim3 g1((N_NODES + 63) / 64, H4 / 128, 2);
    pq_kernel<<<g1, 256>>>(emb, W1, b1);
    edge_kernel<<<N_EDGES / 64, 256>>>(ei, W2, b2, W3, b3, out);
}

// round 4
// speedup vs baseline: 2.0975x; 2.0975x over previous
#include <cuda_runtime.h>
#include <cuda_bf16.h>
#include <cstdint>

#define N_NODES 50000
#define N_EDGES 800000
#define HIDDEN  128
#define H4      512
#define KC      64            // K elements per chunk
#define NCH     8             // 512 / 64
#define TILE_M  128
#define EDGE_BLOCKS (N_EDGES / TILE_M)   // 6250

#define ROWB   144                 // padded bytes per 64-half tile row
#define TSZ    (128 * ROWB)        // 18432 B per tile
#define AH_OFF 0
#define AL_OFF (1 * TSZ)
#define BH_OFF (2 * TSZ)
#define BL_OFF (3 * TSZ)
#define STAGE  (4 * TSZ)           // 73728
#define SMEM_BYTES (2 * STAGE)     // 147456

// Precomputed P = emb @ W1[:128] + b1, Q = emb @ W1[128:]
__device__ float g_P[(size_t)N_NODES * H4];
__device__ float g_Q[(size_t)N_NODES * H4];
__device__ int   g_idx64;
// W2^T hi/lo bf16, padded rows: [chunk][n=128][k=72 halfs]
__device__ __align__(16) unsigned short g_BH2[NCH * 128 * 72];
__device__ __align__(16) unsigned short g_BL2[NCH * 128 * 72];

typedef unsigned long long ull;
typedef unsigned int uint32;

// ---------------- helpers ----------------
__device__ __forceinline__ uint32 smem_u32(const void* p) {
    uint32 a; asm("{ .reg .u64 t; cvta.to.shared.u64 t, %1; cvt.u32.u64 %0, t; }"
                  : "=r"(a) : "l"(p)); return a;
}
__device__ __forceinline__ void ldsm4(uint32& r0, uint32& r1, uint32& r2, uint32& r3, uint32 addr) {
    asm volatile("ldmatrix.sync.aligned.m8n8.x4.shared.b16 {%0,%1,%2,%3}, [%4];"
                 : "=r"(r0), "=r"(r1), "=r"(r2), "=r"(r3) : "r"(addr));
}
__device__ __forceinline__ void mma16816(float* d, const uint32* a, uint32 b0, uint32 b1) {
    asm volatile("mma.sync.aligned.m16n8k16.row.col.f32.bf16.bf16.f32 "
                 "{%0,%1,%2,%3},{%4,%5,%6,%7},{%8,%9},{%0,%1,%2,%3};"
                 : "+f"(d[0]), "+f"(d[1]), "+f"(d[2]), "+f"(d[3])
                 : "r"(a[0]), "r"(a[1]), "r"(a[2]), "r"(a[3]), "r"(b0), "r"(b1));
}
__device__ __forceinline__ void cpasync16(uint32 dst, const void* src) {
    asm volatile("cp.async.cg.shared.global [%0], [%1], 16;" :: "r"(dst), "l"(src) : "memory");
}
#define CP_COMMIT() asm volatile("cp.async.commit_group;" ::: "memory")
#define CP_WAIT0()  asm volatile("cp.async.wait_group 0;" ::: "memory")

__device__ __forceinline__ uint32 cvt_bf16x2(float lo, float hi) {
    uint32 r; asm("cvt.rn.bf16x2.f32 %0, %1, %2;" : "=r"(r) : "f"(hi), "f"(lo)); return r;
}

// f32x2 helpers for pq_kernel
__device__ __forceinline__ ull pk2(float x, float y) {
    ull r; asm("mov.b64 %0, {%1, %2};" : "=l"(r) : "f"(x), "f"(y)); return r;
}
__device__ __forceinline__ void upk2(ull v, float& x, float& y) {
    asm("mov.b64 {%0, %1}, %2;" : "=f"(x), "=f"(y) : "l"(v));
}
__device__ __forceinline__ void fma2(ull& d, ull a, ull b) {
    asm("fma.rn.f32x2 %0, %1, %2, %0;" : "+l"(d) : "l"(a), "l"(b));
}

// ---------------------------------------------------------------------------
// Kernel 0: edge_index dtype detection (int64 vs silently-downcast int32)
// ---------------------------------------------------------------------------
__global__ void detect_kernel(const int* __restrict__ ei32)
{
    int t = threadIdx.x;                 // 128 threads
    int w = ei32[2 * t + 1];
    unsigned ballot = __ballot_sync(0xFFFFFFFFu, w != 0);
    __shared__ int any_nz;
    if (t == 0) any_nz = 0;
    __syncthreads();
    if ((t & 31) == 0 && ballot) atomicOr(&any_nz, 1);
    __syncthreads();
    if (t == 0) g_idx64 = any_nz ? 0 : 1;
}

// ---------------------------------------------------------------------------
// Kernel 0b: W2^T hi/lo bf16 split into padded [chunk][n][72] layout
// ---------------------------------------------------------------------------
__global__ void prep_w2(const float* __restrict__ W2)
{
    int i = blockIdx.x * 256 + threadIdx.x;   // 0..65535 = k*128+n
    int k = i >> 7, n = i & 127;
    float w = W2[i];
    __nv_bfloat16 hb = __float2bfloat16(w);
    float hf = __bfloat162float(hb);
    __nv_bfloat16 lb = __float2bfloat16(w - hf);
    int c = k >> 6, kl = k & 63;
    int idx = c * (128 * 72) + n * 72 + kl;
    g_BH2[idx] = __bfloat16_as_ushort(hb);
    g_BL2[idx] = __bfloat16_as_ushort(lb);
}

// ---------------------------------------------------------------------------
// Kernel 1: P/Q precompute (fp32 SIMT, f32x2) — unchanged
// ---------------------------------------------------------------------------
__global__ __launch_bounds__(256) void pq_kernel(
    const float* __restrict__ emb,
    const float* __restrict__ W1,
    const float* __restrict__ b1)
{
    __shared__ float A_s[64 * 36];
    __shared__ float B_s[32 * 128];

    const int t   = threadIdx.x;
    const int n0  = blockIdx.x * 64;
    const int j0t = blockIdx.y * 128;
    const int z   = blockIdx.z;
    float* gout = z ? g_Q : g_P;
    const float* Wbase = W1 + (size_t)z * HIDDEN * H4;

    ull acc[4][4];
#pragma unroll
    for (int i = 0; i < 4; i++)
#pragma unroll
        for (int p = 0; p < 4; p++) acc[i][p] = 0ull;

    const int e0 = (t >> 4) * 4;
    const int j0 = (t & 15) * 8;

    for (int kc = 0; kc < HIDDEN; kc += 32) {
#pragma unroll
        for (int i = 0; i < 2; i++) {
            int u  = t + i * 256;
            int nl = u >> 3;
            int k4 = (u & 7) * 4;
            int n  = n0 + nl; if (n >= N_NODES) n = N_NODES - 1;
            float4 v = *(const float4*)(emb + (size_t)n * HIDDEN + kc + k4);
            *(float4*)&A_s[nl * 36 + k4] = v;
        }
#pragma unroll
        for (int i = 0; i < 4; i++) {
            int f  = t + i * 256;
            int k  = f >> 5;
            int j4 = (f & 31) * 4;
            float4 v = *(const float4*)(Wbase + (size_t)(kc + k) * H4 + j0t + j4);
            *(float4*)&B_s[k * 128 + j4] = v;
        }
        __syncthreads();
#pragma unroll 8
        for (int kk = 0; kk < 32; kk++) {
            float4 bA = *(float4*)&B_s[kk * 128 + j0];
            float4 bB = *(float4*)&B_s[kk * 128 + j0 + 4];
            ull pb0 = pk2(bA.x, bA.y), pb1 = pk2(bA.z, bA.w);
            ull pb2 = pk2(bB.x, bB.y), pb3 = pk2(bB.z, bB.w);
#pragma unroll
            for (int i = 0; i < 4; i++) {
                float a = A_s[(e0 + i) * 36 + kk];
                ull pa = pk2(a, a);
                fma2(acc[i][0], pa, pb0);
                fma2(acc[i][1], pa, pb1);
                fma2(acc[i][2], pa, pb2);
                fma2(acc[i][3], pa, pb3);
            }
        }
        __syncthreads();
    }

#pragma unroll
    for (int i = 0; i < 4; i++) {
        int n = n0 + e0 + i;
        if (n < N_NODES) {
#pragma unroll
            for (int p = 0; p < 4; p++) {
                float x, y; upk2(acc[i][p], x, y);
                int j = j0t + j0 + p * 2;
                if (z == 0) { x += b1[j]; y += b1[j + 1]; }
                *(float2*)(&gout[(size_t)n * H4 + j]) = make_float2(x, y);
            }
        }
    }
}

// ---------------------------------------------------------------------------
// Kernel 2: warp-MMA edge kernel (mma.sync m16n8k16 bf16, 3-term split).
// 128 edges x 128 outs per block, K=512 in 8 chunks, double-buffered.
// ---------------------------------------------------------------------------
__global__ __launch_bounds__(256, 1) void edge_mma_kernel(
    const void* __restrict__ ei,
    const float* __restrict__ b2,
    const float* __restrict__ W3,
    const float* __restrict__ b3,
    float* __restrict__ out)
{
    extern __shared__ char smem[];
    __shared__ int   s_col[128], s_row[128];
    __shared__ float s_b2[128], s_w3[128];

    const uint32 sb = smem_u32(smem);
    const int t    = threadIdx.x;
    const int lane = t & 31;
    const int w    = t >> 5;
    const long long eb = (long long)blockIdx.x * TILE_M;

    if (t < 128) {
        int c, r;
        if (g_idx64) {
            const long long* p = (const long long*)ei;
            c = (int)p[eb + t]; r = (int)p[(long long)N_EDGES + eb + t];
        } else {
            const int* p = (const int*)ei;
            c = p[eb + t]; r = p[N_EDGES + eb + t];
        }
        c = min(max(c, 0), N_NODES - 1);
        r = min(max(r, 0), N_NODES - 1);
        s_col[t] = c; s_row[t] = r;
    } else {
        int j = t - 128;
        s_b2[j] = b2[j]; s_w3[j] = W3[j];
    }
    __syncthreads();

    // A gather mapping: 2 threads per edge, 32 k-elems each
    const int el = t >> 1;
    const int h  = t & 1;
    const float* Pp = g_P + (size_t)s_col[el] * H4 + h * 32;
    const float* Qp = g_Q + (size_t)s_row[el] * H4 + h * 32;
    const uint32 aStore = (uint32)el * ROWB + (uint32)h * 64;  // + g*16

    // ldmatrix lane addresses
    const uint32 aLd = (uint32)(w * 16 + (lane & 15)) * ROWB + (uint32)(lane >> 4) * 16;
    const uint32 bRow = (uint32)((lane & 7) + ((lane >> 4) << 3));
    const uint32 bLd  = bRow * ROWB + (uint32)((lane >> 3) & 1) * 16;

    float acc[16][4];
#pragma unroll
    for (int nb = 0; nb < 16; nb++)
#pragma unroll
        for (int q = 0; q < 4; q++) acc[nb][q] = 0.f;

    // ---------------- prologue: stage chunk 0 into buffer 0 ----------------
    {
        const uint4* srcH = (const uint4*)g_BH2;      // chunk 0
        const uint4* srcL = (const uint4*)g_BL2;
        for (int u = t; u < 1152; u += 256) {
            cpasync16(sb + BH_OFF + u * 16, srcH + u);
            cpasync16(sb + BL_OFF + u * 16, srcL + u);
        }
        CP_COMMIT();
        float4 pA[8], qA[8];
        const float4* pp = (const float4*)Pp;
        const float4* qq = (const float4*)Qp;
#pragma unroll
        for (int g = 0; g < 8; g++) { pA[g] = pp[g]; qA[g] = qq[g]; }
#pragma unroll
        for (int g = 0; g < 4; g++) {
            float4 p0 = pA[2 * g], p1 = pA[2 * g + 1];
            float4 q0 = qA[2 * g], q1 = qA[2 * g + 1];
            float a0 = fmaxf(p0.x + q0.x, 0.f), a1 = fmaxf(p0.y + q0.y, 0.f);
            float a2 = fmaxf(p0.z + q0.z, 0.f), a3 = fmaxf(p0.w + q0.w, 0.f);
            float a4 = fmaxf(p1.x + q1.x, 0.f), a5 = fmaxf(p1.y + q1.y, 0.f);
            float a6 = fmaxf(p1.z + q1.z, 0.f), a7 = fmaxf(p1.w + q1.w, 0.f);
            uint32 h01 = cvt_bf16x2(a0, a1), h23 = cvt_bf16x2(a2, a3);
            uint32 h45 = cvt_bf16x2(a4, a5), h67 = cvt_bf16x2(a6, a7);
            float f0 = __uint_as_float(h01 << 16), f1 = __uint_as_float(h01 & 0xFFFF0000u);
            float f2 = __uint_as_float(h23 << 16), f3 = __uint_as_float(h23 & 0xFFFF0000u);
            float f4 = __uint_as_float(h45 << 16), f5 = __uint_as_float(h45 & 0xFFFF0000u);
            float f6 = __uint_as_float(h67 << 16), f7 = __uint_as_float(h67 & 0xFFFF0000u);
            uint32 l01 = cvt_bf16x2(a0 - f0, a1 - f1), l23 = cvt_bf16x2(a2 - f2, a3 - f3);
            uint32 l45 = cvt_bf16x2(a4 - f4, a5 - f5), l67 = cvt_bf16x2(a6 - f6, a7 - f7);
            uint32 o = aStore + g * 16;
            *(uint4*)(smem + AH_OFF + o) = make_uint4(h01, h23, h45, h67);
            *(uint4*)(smem + AL_OFF + o) = make_uint4(l01, l23, l45, l67);
        }
        CP_WAIT0();
        __syncthreads();
    }

    // ---------------- main loop ----------------
    for (int i = 0; i < NCH; i++) {
        const int s = i & 1;
        const uint32 bufR = sb + (uint32)s * STAGE;
        const char*  bufWp = smem + (s ^ 1) * STAGE;

        float4 pA[8], qA[8];
        if (i + 1 < NCH) {
            const uint4* srcH = (const uint4*)g_BH2 + (i + 1) * 1152;
            const uint4* srcL = (const uint4*)g_BL2 + (i + 1) * 1152;
            const uint32 bw = sb + (uint32)(s ^ 1) * STAGE;
            for (int u = t; u < 1152; u += 256) {
                cpasync16(bw + BH_OFF + u * 16, srcH + u);
                cpasync16(bw + BL_OFF + u * 16, srcL + u);
            }
            CP_COMMIT();
            const float4* pp = (const float4*)(Pp + (i + 1) * KC);
            const float4* qq = (const float4*)(Qp + (i + 1) * KC);
#pragma unroll
            for (int g = 0; g < 8; g++) { pA[g] = pp[g]; qA[g] = qq[g]; }
        }

        // MMA phase on buffer s
#pragma unroll
        for (int ks = 0; ks < 4; ks++) {
            const uint32 kb = (uint32)ks * 32;
            uint32 ah[4], al[4];
            ldsm4(ah[0], ah[1], ah[2], ah[3], bufR + AH_OFF + aLd + kb);
            ldsm4(al[0], al[1], al[2], al[3], bufR + AL_OFF + aLd + kb);
#pragma unroll
            for (int p = 0; p < 8; p++) {
                uint32 r0, r1, r2, r3;
                ldsm4(r0, r1, r2, r3, bufR + BH_OFF + bLd + (uint32)p * (16 * ROWB) + kb);
                mma16816(acc[2 * p],     ah, r0, r1);
                mma16816(acc[2 * p + 1], ah, r2, r3);
                mma16816(acc[2 * p],     al, r0, r1);
                mma16816(acc[2 * p + 1], al, r2, r3);
                ldsm4(r0, r1, r2, r3, bufR + BL_OFF + bLd + (uint32)p * (16 * ROWB) + kb);
                mma16816(acc[2 * p],     ah, r0, r1);
                mma16816(acc[2 * p + 1], ah, r2, r3);
            }
        }

        if (i + 1 < NCH) {
#pragma unroll
            for (int g = 0; g < 4; g++) {
                float4 p0 = pA[2 * g], p1 = pA[2 * g + 1];
                float4 q0 = qA[2 * g], q1 = qA[2 * g + 1];
                float a0 = fmaxf(p0.x + q0.x, 0.f), a1 = fmaxf(p0.y + q0.y, 0.f);
                float a2 = fmaxf(p0.z + q0.z, 0.f), a3 = fmaxf(p0.w + q0.w, 0.f);
                float a4 = fmaxf(p1.x + q1.x, 0.f), a5 = fmaxf(p1.y + q1.y, 0.f);
                float a6 = fmaxf(p1.z + q1.z, 0.f), a7 = fmaxf(p1.w + q1.w, 0.f);
                uint32 h01 = cvt_bf16x2(a0, a1), h23 = cvt_bf16x2(a2, a3);
                uint32 h45 = cvt_bf16x2(a4, a5), h67 = cvt_bf16x2(a6, a7);
                float f0 = __uint_as_float(h01 << 16), f1 = __uint_as_float(h01 & 0xFFFF0000u);
                float f2 = __uint_as_float(h23 << 16), f3 = __uint_as_float(h23 & 0xFFFF0000u);
                float f4 = __uint_as_float(h45 << 16), f5 = __uint_as_float(h45 & 0xFFFF0000u);
                float f6 = __uint_as_float(h67 << 16), f7 = __uint_as_float(h67 & 0xFFFF0000u);
                uint32 l01 = cvt_bf16x2(a0 - f0, a1 - f1), l23 = cvt_bf16x2(a2 - f2, a3 - f3);
                uint32 l45 = cvt_bf16x2(a4 - f4, a5 - f5), l67 = cvt_bf16x2(a6 - f6, a7 - f7);
                uint32 o = aStore + g * 16;
                *(uint4*)(bufWp + AH_OFF + o) = make_uint4(h01, h23, h45, h67);
                *(uint4*)(bufWp + AL_OFF + o) = make_uint4(l01, l23, l45, l67);
            }
        }
        CP_WAIT0();
        __syncthreads();
    }

    // ---------------- epilogue: fold layer 3 ----------------
    const int g4 = lane >> 2;
    const int t4 = lane & 3;
    float sA = 0.f, sB = 0.f;
#pragma unroll
    for (int nb = 0; nb < 16; nb++) {
        int c0 = nb * 8 + 2 * t4;
        int c1 = c0 + 1;
        sA += fmaxf(acc[nb][0] + s_b2[c0], 0.f) * s_w3[c0];
        sA += fmaxf(acc[nb][1] + s_b2[c1], 0.f) * s_w3[c1];
        sB += fmaxf(acc[nb][2] + s_b2[c0], 0.f) * s_w3[c0];
        sB += fmaxf(acc[nb][3] + s_b2[c1], 0.f) * s_w3[c1];
    }
    sA += __shfl_xor_sync(0xFFFFFFFFu, sA, 1);
    sA += __shfl_xor_sync(0xFFFFFFFFu, sA, 2);
    sB += __shfl_xor_sync(0xFFFFFFFFu, sB, 1);
    sB += __shfl_xor_sync(0xFFFFFFFFu, sB, 2);
    if (t4 == 0) {
        float b3v = b3[0];
        long long rA = eb + w * 16 + g4;
        out[rA]     = sA + b3v;
        out[rA + 8] = sB + b3v;
    }
}

extern "C" void kernel_launch(void* const* d_in, const int* in_sizes, int n_in,
                              void* d_out, int out_size)
{
    const float* emb = (const float*)d_in[0];
    const void*  ei  = d_in[1];
    const float* W1  = (const float*)d_in[2];
    const float* b1  = (const float*)d_in[3];
    const float* W2  = (const float*)d_in[4];
    const float* b2  = (const float*)d_in[5];
    const float* W3  = (const float*)d_in[6];
    const float* b3  = (const float*)d_in[7];
    float* out = (float*)d_out;
    (void)in_sizes; (void)n_in; (void)out_size;

    cudaFuncSetAttribute(edge_mma_kernel,
                         cudaFuncAttributeMaxDynamicSharedMemorySize, SMEM_BYTES);

    detect_kernel<<<1, 128>>>((const int*)ei);
    prep_w2<<<256, 256>>>(W2);
    dim3 g1((N_NODES + 63) / 64, H4 / 128, 2);
    pq_kernel<<<g1, 256>>>(emb, W1, b1);
    edge_mma_kernel<<<EDGE_BLOCKS, 256, SMEM_BYTES>>>(ei, b2, W3, b3, out);
}